// round 2
// baseline (speedup 1.0000x reference)
#include <cuda_runtime.h>

#define NN   10000
#define EE   160000
#define RNAD 2000
#define PROTD 100
#define EMBD 128
#define HIDD 128
#define NH   4
#define DIN  256
#define DMID 512

// ---------------- scratch (static device globals; no runtime allocation) ---
__device__ float    g_xin[NN * DIN];
__device__ float    g_xs [NN * DMID];
__device__ float    g_xd [NN * DMID];
__device__ float    g_lin[NN * DMID];
__device__ float    g_gat[NN * DMID];
__device__ float    g_h  [NN * DMID];
__device__ float    g_as [NN * NH];
__device__ float    g_ad [NN * NH];
__device__ unsigned g_menc[NN * NH];
__device__ float    g_den[NN * NH];
__device__ float    g_alpha[EE * NH];
__device__ float    g_t  [NN * EMBD];
__device__ int      g_src[EE];
__device__ int      g_dst[EE];
__device__ int      g_is64;

// ---------------- edge-index dtype detect + decode -------------------------
// If data is int64 (LE) with values in [0,10000), every odd 32-bit word is 0.
// If data is int32, odd words are node ids (nonzero with overwhelming prob
// across 2048 samples). Deterministic for fixed input.
__global__ void detect_fmt(const unsigned* __restrict__ w) {
    if (threadIdx.x == 0 && blockIdx.x == 0) {
        unsigned acc = 0;
        for (int i = 1; i < 4096; i += 2) acc |= w[i];
        g_is64 = (acc == 0u) ? 1 : 0;
    }
}

__global__ void decode_idx(const void* __restrict__ ei,
                           int* __restrict__ src, int* __restrict__ dst) {
    int i = blockIdx.x * blockDim.x + threadIdx.x;
    if (i >= 2 * EE) return;
    long long v;
    if (g_is64) v = ((const long long*)ei)[i];
    else        v = (long long)((const int*)ei)[i];
    int vi = (int)v;
    vi = vi < 0 ? 0 : (vi >= NN ? NN - 1 : vi);
    if (i < EE) src[i] = vi;
    else        dst[i - EE] = vi;
}

// ---------------- utility -------------------------------------------------
__global__ void zero_u32(unsigned* p, int n) {
    int i = blockIdx.x * blockDim.x + threadIdx.x;
    int stride = gridDim.x * blockDim.x;
    for (; i < n; i += stride) p[i] = 0u;
}

__device__ __forceinline__ unsigned fenc(float f) {
    unsigned u = __float_as_uint(f);
    return (u & 0x80000000u) ? ~u : (u | 0x80000000u);
}
__device__ __forceinline__ float fdec(unsigned u) {
    return (u & 0x80000000u) ? __uint_as_float(u & 0x7fffffffu) : __uint_as_float(~u);
}

// ---------------- SGEMM: C[M,Nc] = A[M,K]@B[K,Nc] (+bias)(+relu) -----------
#define BM 64
#define BN 64
#define BK 16
__global__ void sgemm_kernel(const float* __restrict__ A, int lda,
                             const float* __restrict__ B, int ldb,
                             float* __restrict__ C, int ldc,
                             const float* __restrict__ bias,
                             int M, int Nc, int K, int relu) {
    __shared__ float As[BK][BM + 1];
    __shared__ float Bs[BK][BN];
    const int tid = threadIdx.y * 16 + threadIdx.x;   // 0..255
    const int blockRow = blockIdx.y * BM;
    const int blockCol = blockIdx.x * BN;
    float acc[4][4] = {};

    for (int k0 = 0; k0 < K; k0 += BK) {
        #pragma unroll
        for (int i = 0; i < 4; i++) {
            int idx = tid + i * 256;
            int r  = idx / BK;
            int kk = idx % BK;
            int gr = blockRow + r, gk = k0 + kk;
            As[kk][r] = (gr < M && gk < K) ? A[(size_t)gr * lda + gk] : 0.f;
        }
        #pragma unroll
        for (int i = 0; i < 4; i++) {
            int idx = tid + i * 256;
            int kk = idx / BN;
            int c  = idx % BN;
            int gk = k0 + kk, gc = blockCol + c;
            Bs[kk][c] = (gk < K && gc < Nc) ? B[(size_t)gk * ldb + gc] : 0.f;
        }
        __syncthreads();
        #pragma unroll
        for (int kk = 0; kk < BK; kk++) {
            float a[4], b[4];
            #pragma unroll
            for (int i = 0; i < 4; i++) a[i] = As[kk][threadIdx.y * 4 + i];
            #pragma unroll
            for (int j = 0; j < 4; j++) b[j] = Bs[kk][threadIdx.x * 4 + j];
            #pragma unroll
            for (int i = 0; i < 4; i++)
                #pragma unroll
                for (int j = 0; j < 4; j++)
                    acc[i][j] += a[i] * b[j];
        }
        __syncthreads();
    }
    #pragma unroll
    for (int i = 0; i < 4; i++) {
        int gr = blockRow + threadIdx.y * 4 + i;
        if (gr >= M) continue;
        #pragma unroll
        for (int j = 0; j < 4; j++) {
            int gc = blockCol + threadIdx.x * 4 + j;
            if (gc >= Nc) continue;
            float v = acc[i][j];
            if (bias) v += bias[gc];
            if (relu) v = fmaxf(v, 0.f);
            C[(size_t)gr * ldc + gc] = v;
        }
    }
}

// ---------------- GAT: attention scores per (node, head) -------------------
__global__ void att_scores(const float* __restrict__ xs, const float* __restrict__ xd,
                           const float* __restrict__ att_s, const float* __restrict__ att_d,
                           float* __restrict__ a_s, float* __restrict__ a_d) {
    int n = blockIdx.x;
    int w = threadIdx.x >> 5;     // head
    int lane = threadIdx.x & 31;
    size_t base = (size_t)n * DMID + w * HIDD;
    float s = 0.f, d = 0.f;
    #pragma unroll
    for (int c = lane; c < HIDD; c += 32) {
        s += xs[base + c] * att_s[w * HIDD + c];
        d += xd[base + c] * att_d[w * HIDD + c];
    }
    #pragma unroll
    for (int o = 16; o > 0; o >>= 1) {
        s += __shfl_down_sync(0xffffffffu, s, o);
        d += __shfl_down_sync(0xffffffffu, d, o);
    }
    if (lane == 0) { a_s[n * NH + w] = s; a_d[n * NH + w] = d; }
}

// ---------------- GAT edge passes ------------------------------------------
__global__ void edge_alpha_max(const int* __restrict__ src, const int* __restrict__ dst,
                               const float* __restrict__ a_s, const float* __restrict__ a_d,
                               float* __restrict__ alpha, unsigned* __restrict__ menc) {
    int idx = blockIdx.x * blockDim.x + threadIdx.x;
    if (idx >= EE * NH) return;
    int e = idx >> 2, h = idx & 3;
    int s = src[e], d = dst[e];
    float a = a_s[s * NH + h] + a_d[d * NH + h];
    a = a > 0.f ? a : 0.2f * a;                 // leaky_relu(0.2)
    alpha[idx] = a;
    atomicMax(&menc[d * NH + h], fenc(a));
}

__global__ void edge_exp_sum(const int* __restrict__ dst,
                             float* __restrict__ alpha,
                             const unsigned* __restrict__ menc,
                             float* __restrict__ den) {
    int idx = blockIdx.x * blockDim.x + threadIdx.x;
    if (idx >= EE * NH) return;
    int e = idx >> 2, h = idx & 3;
    int d = dst[e];
    float a = expf(alpha[idx] - fdec(menc[d * NH + h]));
    alpha[idx] = a;
    atomicAdd(&den[d * NH + h], a);
}

__global__ void edge_norm(const int* __restrict__ dst,
                          float* __restrict__ alpha,
                          const float* __restrict__ den) {
    int idx = blockIdx.x * blockDim.x + threadIdx.x;
    if (idx >= EE * NH) return;
    int e = idx >> 2, h = idx & 3;
    int d = dst[e];
    alpha[idx] = alpha[idx] / (den[d * NH + h] + 1e-16f);
}

__global__ void edge_scatter(const int* __restrict__ src, const int* __restrict__ dst,
                             const float* __restrict__ alpha,
                             const float* __restrict__ xs,
                             float* __restrict__ gat) {
    int idx = blockIdx.x * blockDim.x + threadIdx.x;
    if (idx >= EE * 128) return;
    int e = idx >> 7;
    int r = idx & 127;
    int h = r >> 5;
    int q = (r & 31) << 2;
    float w = alpha[(e << 2) + h];
    int s = src[e], d = dst[e];
    const float4 v = *(const float4*)(xs + (size_t)s * DMID + h * HIDD + q);
    float* o = gat + (size_t)d * DMID + h * HIDD + q;
    atomicAdd(o + 0, v.x * w);
    atomicAdd(o + 1, v.y * w);
    atomicAdd(o + 2, v.z * w);
    atomicAdd(o + 3, v.w * w);
}

// ---------------- residual (+bias) + LayerNorm + ReLU ----------------------
__global__ void resid_ln_relu(const float* __restrict__ gat, const float* __restrict__ cb,
                              const float* __restrict__ lin, const float* __restrict__ g,
                              const float* __restrict__ b, float* __restrict__ out) {
    int row = blockIdx.x;
    int t = threadIdx.x;                     // 256 threads, 2 elems each
    size_t base = (size_t)row * DMID;
    float v0 = gat[base + t]       + cb[t]       + lin[base + t];
    float v1 = gat[base + 256 + t] + cb[256 + t] + lin[base + 256 + t];
    float s = v0 + v1;
    float ss = v0 * v0 + v1 * v1;
    #pragma unroll
    for (int o = 16; o > 0; o >>= 1) {
        s  += __shfl_down_sync(0xffffffffu, s, o);
        ss += __shfl_down_sync(0xffffffffu, ss, o);
    }
    __shared__ float shs[8], shss[8];
    __shared__ float mu_sh, inv_sh;
    int w = t >> 5, lane = t & 31;
    if (lane == 0) { shs[w] = s; shss[w] = ss; }
    __syncthreads();
    if (t == 0) {
        float S = 0.f, SS = 0.f;
        #pragma unroll
        for (int i = 0; i < 8; i++) { S += shs[i]; SS += shss[i]; }
        float mu = S * (1.f / DMID);
        float var = SS * (1.f / DMID) - mu * mu;
        mu_sh = mu;
        inv_sh = rsqrtf(var + 1e-5f);
    }
    __syncthreads();
    float mu = mu_sh, inv = inv_sh;
    out[base + t]       = fmaxf((v0 - mu) * inv * g[t]       + b[t],       0.f);
    out[base + 256 + t] = fmaxf((v1 - mu) * inv * g[256 + t] + b[256 + t], 0.f);
}

// ---------------- residual (+bias), no norm --------------------------------
__global__ void resid_add(const float* __restrict__ gat, const float* __restrict__ cb,
                          const float* __restrict__ lin, float* __restrict__ out, int n) {
    int i = blockIdx.x * blockDim.x + threadIdx.x;
    int stride = gridDim.x * blockDim.x;
    for (; i < n; i += stride)
        out[i] = gat[i] + cb[i & (DMID - 1)] + lin[i];
}

// ---------------- host ------------------------------------------------------
static void gemm(const float* A, int lda, const float* B, int ldb,
                 float* C, int ldc, const float* bias,
                 int M, int Nc, int K, int relu) {
    dim3 grid((Nc + BN - 1) / BN, (M + BM - 1) / BM), blk(16, 16);
    sgemm_kernel<<<grid, blk>>>(A, lda, B, ldb, C, ldc, bias, M, Nc, K, relu);
}

extern "C" void kernel_launch(void* const* d_in, const int* in_sizes, int n_in,
                              void* d_out, int out_size) {
    const float* x      = (const float*)d_in[0];
    const void*  ei     = d_in[1];
    const float* W_rna  = (const float*)d_in[2];
    const float* b_rna  = (const float*)d_in[3];
    const float* W_prot = (const float*)d_in[4];
    const float* b_prot = (const float*)d_in[5];
    const float* c1_Ws  = (const float*)d_in[6];
    const float* c1_Wd  = (const float*)d_in[7];
    const float* c1_as  = (const float*)d_in[8];
    const float* c1_ad  = (const float*)d_in[9];
    const float* c1_b   = (const float*)d_in[10];
    const float* l1_W   = (const float*)d_in[11];
    const float* l1_b   = (const float*)d_in[12];
    const float* ln_g   = (const float*)d_in[13];
    const float* ln_b   = (const float*)d_in[14];
    const float* c2_Ws  = (const float*)d_in[15];
    const float* c2_Wd  = (const float*)d_in[16];
    const float* c2_as  = (const float*)d_in[17];
    const float* c2_ad  = (const float*)d_in[18];
    const float* c2_b   = (const float*)d_in[19];
    const float* l2_W   = (const float*)d_in[20];
    const float* l2_b   = (const float*)d_in[21];
    const float* agg_W  = (const float*)d_in[22];
    const float* agg_b  = (const float*)d_in[23];
    const float* dr_W   = (const float*)d_in[24];
    const float* dr_b   = (const float*)d_in[25];
    const float* dp_W   = (const float*)d_in[26];
    const float* dp_b   = (const float*)d_in[27];
    const float* rr_W   = (const float*)d_in[28];
    const float* rr_b   = (const float*)d_in[29];
    const float* rp_W   = (const float*)d_in[30];
    const float* rp_b   = (const float*)d_in[31];

    float* out = (float*)d_out;
    float* out_rna  = out;                                  // [NN, 2000]
    float* out_prot = out + (size_t)NN * RNAD;              // [NN, 100]
    float* out_emb  = out + (size_t)NN * (RNAD + PROTD);    // [NN, 128]

    float *xin, *xs, *xd, *lin, *gat, *h, *as_, *ad_, *den, *alpha, *t;
    unsigned* menc;
    int *srcI, *dstI;
    cudaGetSymbolAddress((void**)&xin,  g_xin);
    cudaGetSymbolAddress((void**)&xs,   g_xs);
    cudaGetSymbolAddress((void**)&xd,   g_xd);
    cudaGetSymbolAddress((void**)&lin,  g_lin);
    cudaGetSymbolAddress((void**)&gat,  g_gat);
    cudaGetSymbolAddress((void**)&h,    g_h);
    cudaGetSymbolAddress((void**)&as_,  g_as);
    cudaGetSymbolAddress((void**)&ad_,  g_ad);
    cudaGetSymbolAddress((void**)&menc, g_menc);
    cudaGetSymbolAddress((void**)&den,  g_den);
    cudaGetSymbolAddress((void**)&alpha,g_alpha);
    cudaGetSymbolAddress((void**)&t,    g_t);
    cudaGetSymbolAddress((void**)&srcI, g_src);
    cudaGetSymbolAddress((void**)&dstI, g_dst);

    const int EB = 256;
    const int nEH = EE * NH;
    const int nScatter = EE * 128;

    // ---- decode edge indices (int32/int64 agnostic, clamped) --------------
    detect_fmt<<<1, 32>>>((const unsigned*)ei);
    decode_idx<<<(2 * EE + EB - 1) / EB, EB>>>(ei, srcI, dstI);

    // ---- input embeddings: xin = [x@W_rna+b | x@W_prot+b] -----------------
    gemm(x,          RNAD + PROTD, W_rna,  EMBD, xin,        DIN, b_rna,  NN, EMBD, RNAD,  0);
    gemm(x + RNAD,   RNAD + PROTD, W_prot, EMBD, xin + EMBD, DIN, b_prot, NN, EMBD, PROTD, 0);

    // ================= Block 1 =============================================
    gemm(xin, DIN, c1_Ws, DMID, xs,  DMID, nullptr, NN, DMID, DIN, 0);
    gemm(xin, DIN, c1_Wd, DMID, xd,  DMID, nullptr, NN, DMID, DIN, 0);
    gemm(xin, DIN, l1_W,  DMID, lin, DMID, l1_b,    NN, DMID, DIN, 0);

    att_scores<<<NN, 128>>>(xs, xd, c1_as, c1_ad, as_, ad_);
    zero_u32<<<512, 256>>>((unsigned*)gat, NN * DMID);
    zero_u32<<<64, 256>>>((unsigned*)den, NN * NH);
    zero_u32<<<64, 256>>>(menc, NN * NH);

    edge_alpha_max<<<(nEH + EB - 1) / EB, EB>>>(srcI, dstI, as_, ad_, alpha, menc);
    edge_exp_sum  <<<(nEH + EB - 1) / EB, EB>>>(dstI, alpha, menc, den);
    edge_norm     <<<(nEH + EB - 1) / EB, EB>>>(dstI, alpha, den);
    edge_scatter  <<<(nScatter + EB - 1) / EB, EB>>>(srcI, dstI, alpha, xs, gat);

    resid_ln_relu<<<NN, 256>>>(gat, c1_b, lin, ln_g, ln_b, h);

    // ================= Block 2 =============================================
    gemm(h, DMID, c2_Ws, DMID, xs,  DMID, nullptr, NN, DMID, DMID, 0);
    gemm(h, DMID, c2_Wd, DMID, xd,  DMID, nullptr, NN, DMID, DMID, 0);
    gemm(h, DMID, l2_W,  DMID, lin, DMID, l2_b,    NN, DMID, DMID, 0);

    att_scores<<<NN, 128>>>(xs, xd, c2_as, c2_ad, as_, ad_);
    zero_u32<<<512, 256>>>((unsigned*)gat, NN * DMID);
    zero_u32<<<64, 256>>>((unsigned*)den, NN * NH);
    zero_u32<<<64, 256>>>(menc, NN * NH);

    edge_alpha_max<<<(nEH + EB - 1) / EB, EB>>>(srcI, dstI, as_, ad_, alpha, menc);
    edge_exp_sum  <<<(nEH + EB - 1) / EB, EB>>>(dstI, alpha, menc, den);
    edge_norm     <<<(nEH + EB - 1) / EB, EB>>>(dstI, alpha, den);
    edge_scatter  <<<(nScatter + EB - 1) / EB, EB>>>(srcI, dstI, alpha, xs, gat);

    resid_add<<<512, 256>>>(gat, c2_b, lin, h, NN * DMID);

    // ================= Heads ===============================================
    gemm(h, DMID, agg_W, EMBD, out_emb, EMBD, agg_b, NN, EMBD, DMID, 1);   // emb (relu)

    gemm(out_emb, EMBD, dr_W, EMBD, t, EMBD, dr_b, NN, EMBD, EMBD, 0);     // t1
    gemm(t, EMBD, rr_W, RNAD, out_rna, RNAD, rr_b, NN, RNAD, EMBD, 0);     // rna_recon

    gemm(out_emb, EMBD, dp_W, EMBD, t, EMBD, dp_b, NN, EMBD, EMBD, 0);     // t2
    gemm(t, EMBD, rp_W, PROTD, out_prot, PROTD, rp_b, NN, PROTD, EMBD, 0); // prot_recon
}

// round 3
// speedup vs baseline: 1.3771x; 1.3771x over previous
#include <cuda_runtime.h>
#include <cstdint>

#define NN   10000
#define EE   160000
#define RNAD 2000
#define PROTD 100
#define EMBD 128
#define HIDD 128
#define NH   4
#define DIN  256
#define DMID 512

// ---------------- scratch (static device globals; no runtime allocation) ---
__device__ float    g_xin[NN * DIN];
__device__ float    g_xs [NN * DMID];
__device__ float    g_xd [NN * DMID];
__device__ float    g_lin[NN * DMID];
__device__ float    g_gat[NN * DMID];
__device__ float    g_h  [NN * DMID];
__device__ float    g_as [NN * NH];
__device__ float    g_ad [NN * NH];
__device__ unsigned g_menc[NN * NH];
__device__ float    g_den[NN * NH];
__device__ float    g_alpha[EE * NH];
__device__ float    g_t  [NN * EMBD];
__device__ int      g_src[EE];
__device__ int      g_dst[EE];
__device__ int      g_is64;

// ---------------- edge-index dtype detect + decode -------------------------
__global__ void detect_fmt(const unsigned* __restrict__ w) {
    if (threadIdx.x == 0 && blockIdx.x == 0) {
        unsigned acc = 0;
        for (int i = 1; i < 4096; i += 2) acc |= w[i];
        g_is64 = (acc == 0u) ? 1 : 0;
    }
}

__global__ void decode_idx(const void* __restrict__ ei,
                           int* __restrict__ src, int* __restrict__ dst) {
    int i = blockIdx.x * blockDim.x + threadIdx.x;
    if (i >= 2 * EE) return;
    long long v;
    if (g_is64) v = ((const long long*)ei)[i];
    else        v = (long long)((const int*)ei)[i];
    int vi = (int)v;
    vi = vi < 0 ? 0 : (vi >= NN ? NN - 1 : vi);
    if (i < EE) src[i] = vi;
    else        dst[i - EE] = vi;
}

// ---------------- utility -------------------------------------------------
__global__ void zero_u32(unsigned* p, int n) {
    int i = blockIdx.x * blockDim.x + threadIdx.x;
    int stride = gridDim.x * blockDim.x;
    for (; i < n; i += stride) p[i] = 0u;
}

__device__ __forceinline__ unsigned fenc(float f) {
    unsigned u = __float_as_uint(f);
    return (u & 0x80000000u) ? ~u : (u | 0x80000000u);
}
__device__ __forceinline__ float fdec(unsigned u) {
    return (u & 0x80000000u) ? __uint_as_float(u & 0x7fffffffu) : __uint_as_float(~u);
}

// ============================================================================
// Tensor-core GEMM: C[M,N] = A[M,K] @ B[K,N] (+bias)(+relu), fp32 in/out,
// 3xTF32 decomposition (hi*hi + lo*hi + hi*lo) -> ~fp32 accuracy.
// Tiles: 128x128x32, 256 threads (8 warps, 2x4), warp tile 64x32,
// mma.sync.m16n8k8, cp.async 2-stage pipeline.
// ============================================================================
#define TBM 128
#define TBN 128
#define TBK 32
#define A_STRIDE 36     // 128 rows x 36 floats (pad 4) -> conflict-free frag loads
#define B_STRIDE 136    // 32 rows x 136 floats (pad 8) -> conflict-free frag loads
#define A_TILE (TBM * A_STRIDE)
#define B_TILE (TBK * B_STRIDE)
#define SMEM_FLOATS (2 * A_TILE + 2 * B_TILE)

__device__ __forceinline__ void cp_async16(uint32_t smem_addr, const void* gptr, int sz) {
    asm volatile("cp.async.ca.shared.global [%0], [%1], 16, %2;\n"
                 :: "r"(smem_addr), "l"(gptr), "r"(sz));
}
__device__ __forceinline__ void cp_commit() {
    asm volatile("cp.async.commit_group;\n");
}
__device__ __forceinline__ void split_tf32(float x, uint32_t& hi, uint32_t& lo) {
    uint32_t h;
    asm("cvt.rna.tf32.f32 %0, %1;" : "=r"(h) : "f"(x));
    float r = x - __uint_as_float(h);
    uint32_t l;
    asm("cvt.rna.tf32.f32 %0, %1;" : "=r"(l) : "f"(r));
    hi = h; lo = l;
}
__device__ __forceinline__ void mma_tf32(float* c, uint32_t a0, uint32_t a1,
                                         uint32_t a2, uint32_t a3,
                                         uint32_t b0, uint32_t b1) {
    asm volatile(
        "mma.sync.aligned.m16n8k8.row.col.f32.tf32.tf32.f32 "
        "{%0,%1,%2,%3}, {%4,%5,%6,%7}, {%8,%9}, {%0,%1,%2,%3};"
        : "+f"(c[0]), "+f"(c[1]), "+f"(c[2]), "+f"(c[3])
        : "r"(a0), "r"(a1), "r"(a2), "r"(a3), "r"(b0), "r"(b1));
}

__global__ void __launch_bounds__(256)
tf32_gemm_kernel(const float* __restrict__ A, int lda,
                 const float* __restrict__ B, int ldb,
                 float* __restrict__ C, int ldc,
                 const float* __restrict__ bias,
                 int M, int N, int K, int relu) {
    extern __shared__ float smem[];
    float* As = smem;                    // [2][128][A_STRIDE]
    float* Bs = smem + 2 * A_TILE;       // [2][32][B_STRIDE]

    const int tid  = threadIdx.x;
    const int lane = tid & 31;
    const int warp = tid >> 5;
    const int wr = warp >> 2;            // 0..1 -> 64 rows
    const int wc = warp & 3;             // 0..3 -> 32 cols
    const int group = lane >> 2;         // 0..7
    const int tig   = lane & 3;          // 0..3
    const int blockRow = blockIdx.y * TBM;
    const int blockCol = blockIdx.x * TBN;

    const int numTiles = (K + TBK - 1) / TBK;

    // ---- async tile loader -------------------------------------------------
    // A: 128x32 floats = 1024 float4, 256 thr -> 4 each. row = tid/8 (+32*p), col4 = (tid%8)*4
    // B: 32x128 floats = 1024 float4, 256 thr -> 4 each. row = tid/32 (+8*p), col4 = (tid%32)*4
    auto load_tiles = [&](int kt, int stage) {
        int k0 = kt * TBK;
        float* as = As + stage * A_TILE;
        float* bs = Bs + stage * B_TILE;
        int ar = tid >> 3;               // 0..31
        int ac = (tid & 7) * 4;          // 0..28
        #pragma unroll
        for (int p = 0; p < 4; p++) {
            int r = ar + p * 32;
            int gr = blockRow + r;
            int gc = k0 + ac;
            bool ok = (gr < M) && (gc < K);
            const float* src = ok ? (A + (size_t)gr * lda + gc) : A;
            uint32_t dst = (uint32_t)__cvta_generic_to_shared(as + r * A_STRIDE + ac);
            cp_async16(dst, src, ok ? 16 : 0);
        }
        int br = tid >> 5;               // 0..7
        int bc = (tid & 31) * 4;         // 0..124
        #pragma unroll
        for (int p = 0; p < 4; p++) {
            int r = br + p * 8;
            int gk = k0 + r;
            int gc = blockCol + bc;
            bool ok = (gk < K) && (gc < N);
            const float* src = ok ? (B + (size_t)gk * ldb + gc) : B;
            uint32_t dst = (uint32_t)__cvta_generic_to_shared(bs + r * B_STRIDE + bc);
            cp_async16(dst, src, ok ? 16 : 0);
        }
        cp_commit();
    };

    float acc[4][4][4];
    #pragma unroll
    for (int i = 0; i < 4; i++)
        #pragma unroll
        for (int j = 0; j < 4; j++)
            #pragma unroll
            for (int r = 0; r < 4; r++)
                acc[i][j][r] = 0.f;

    load_tiles(0, 0);

    for (int kt = 0; kt < numTiles; kt++) {
        int stage = kt & 1;
        if (kt + 1 < numTiles) {
            load_tiles(kt + 1, stage ^ 1);
            asm volatile("cp.async.wait_group 1;\n");
        } else {
            asm volatile("cp.async.wait_group 0;\n");
        }
        __syncthreads();

        const float* as = As + stage * A_TILE;
        const float* bs = Bs + stage * B_TILE;

        #pragma unroll
        for (int ks = 0; ks < TBK / 8; ks++) {
            int k0 = ks * 8;
            // B fragments for 4 n-tiles
            uint32_t bh[4][2], bl[4][2];
            #pragma unroll
            for (int j = 0; j < 4; j++) {
                int col = wc * 32 + j * 8 + group;
                float b0 = bs[(k0 + tig) * B_STRIDE + col];
                float b1 = bs[(k0 + tig + 4) * B_STRIDE + col];
                split_tf32(b0, bh[j][0], bl[j][0]);
                split_tf32(b1, bh[j][1], bl[j][1]);
            }
            #pragma unroll
            for (int i = 0; i < 4; i++) {
                int row = wr * 64 + i * 16;
                float a0 = as[(row + group) * A_STRIDE + k0 + tig];
                float a1 = as[(row + group + 8) * A_STRIDE + k0 + tig];
                float a2 = as[(row + group) * A_STRIDE + k0 + tig + 4];
                float a3 = as[(row + group + 8) * A_STRIDE + k0 + tig + 4];
                uint32_t ah[4], al[4];
                split_tf32(a0, ah[0], al[0]);
                split_tf32(a1, ah[1], al[1]);
                split_tf32(a2, ah[2], al[2]);
                split_tf32(a3, ah[3], al[3]);
                #pragma unroll
                for (int j = 0; j < 4; j++) {
                    mma_tf32(acc[i][j], ah[0], ah[1], ah[2], ah[3], bh[j][0], bh[j][1]);
                    mma_tf32(acc[i][j], al[0], al[1], al[2], al[3], bh[j][0], bh[j][1]);
                    mma_tf32(acc[i][j], ah[0], ah[1], ah[2], ah[3], bl[j][0], bl[j][1]);
                }
            }
        }
        __syncthreads();
    }

    // ---- epilogue -----------------------------------------------------------
    #pragma unroll
    for (int i = 0; i < 4; i++) {
        int r0 = blockRow + wr * 64 + i * 16 + group;
        int r1 = r0 + 8;
        #pragma unroll
        for (int j = 0; j < 4; j++) {
            int gc = blockCol + wc * 32 + j * 8 + tig * 2;
            if (gc < N) {
                float bi0 = bias ? bias[gc] : 0.f;
                float bi1 = bias ? bias[gc + 1] : 0.f;
                if (r0 < M) {
                    float v0 = acc[i][j][0] + bi0;
                    float v1 = acc[i][j][1] + bi1;
                    if (relu) { v0 = fmaxf(v0, 0.f); v1 = fmaxf(v1, 0.f); }
                    C[(size_t)r0 * ldc + gc]     = v0;
                    C[(size_t)r0 * ldc + gc + 1] = v1;
                }
                if (r1 < M) {
                    float v2 = acc[i][j][2] + bi0;
                    float v3 = acc[i][j][3] + bi1;
                    if (relu) { v2 = fmaxf(v2, 0.f); v3 = fmaxf(v3, 0.f); }
                    C[(size_t)r1 * ldc + gc]     = v2;
                    C[(size_t)r1 * ldc + gc + 1] = v3;
                }
            }
        }
    }
}

// ---------------- GAT: attention scores per (node, head) -------------------
__global__ void att_scores(const float* __restrict__ xs, const float* __restrict__ xd,
                           const float* __restrict__ att_s, const float* __restrict__ att_d,
                           float* __restrict__ a_s, float* __restrict__ a_d) {
    int n = blockIdx.x;
    int w = threadIdx.x >> 5;     // head
    int lane = threadIdx.x & 31;
    size_t base = (size_t)n * DMID + w * HIDD;
    float s = 0.f, d = 0.f;
    #pragma unroll
    for (int c = lane; c < HIDD; c += 32) {
        s += xs[base + c] * att_s[w * HIDD + c];
        d += xd[base + c] * att_d[w * HIDD + c];
    }
    #pragma unroll
    for (int o = 16; o > 0; o >>= 1) {
        s += __shfl_down_sync(0xffffffffu, s, o);
        d += __shfl_down_sync(0xffffffffu, d, o);
    }
    if (lane == 0) { a_s[n * NH + w] = s; a_d[n * NH + w] = d; }
}

// ---------------- GAT edge passes ------------------------------------------
__global__ void edge_alpha_max(const int* __restrict__ src, const int* __restrict__ dst,
                               const float* __restrict__ a_s, const float* __restrict__ a_d,
                               float* __restrict__ alpha, unsigned* __restrict__ menc) {
    int idx = blockIdx.x * blockDim.x + threadIdx.x;
    if (idx >= EE * NH) return;
    int e = idx >> 2, h = idx & 3;
    int s = src[e], d = dst[e];
    float a = a_s[s * NH + h] + a_d[d * NH + h];
    a = a > 0.f ? a : 0.2f * a;                 // leaky_relu(0.2)
    alpha[idx] = a;
    atomicMax(&menc[d * NH + h], fenc(a));
}

__global__ void edge_exp_sum(const int* __restrict__ dst,
                             float* __restrict__ alpha,
                             const unsigned* __restrict__ menc,
                             float* __restrict__ den) {
    int idx = blockIdx.x * blockDim.x + threadIdx.x;
    if (idx >= EE * NH) return;
    int e = idx >> 2, h = idx & 3;
    int d = dst[e];
    float a = expf(alpha[idx] - fdec(menc[d * NH + h]));
    alpha[idx] = a;
    atomicAdd(&den[d * NH + h], a);
}

__global__ void edge_norm(const int* __restrict__ dst,
                          float* __restrict__ alpha,
                          const float* __restrict__ den) {
    int idx = blockIdx.x * blockDim.x + threadIdx.x;
    if (idx >= EE * NH) return;
    int e = idx >> 2, h = idx & 3;
    int d = dst[e];
    alpha[idx] = alpha[idx] / (den[d * NH + h] + 1e-16f);
}

__global__ void edge_scatter(const int* __restrict__ src, const int* __restrict__ dst,
                             const float* __restrict__ alpha,
                             const float* __restrict__ xs,
                             float* __restrict__ gat) {
    int idx = blockIdx.x * blockDim.x + threadIdx.x;
    if (idx >= EE * 128) return;
    int e = idx >> 7;
    int r = idx & 127;
    int h = r >> 5;
    int q = (r & 31) << 2;
    float w = alpha[(e << 2) + h];
    int s = src[e], d = dst[e];
    const float4 v = *(const float4*)(xs + (size_t)s * DMID + h * HIDD + q);
    float* o = gat + (size_t)d * DMID + h * HIDD + q;
    atomicAdd(o + 0, v.x * w);
    atomicAdd(o + 1, v.y * w);
    atomicAdd(o + 2, v.z * w);
    atomicAdd(o + 3, v.w * w);
}

// ---------------- residual (+bias) + LayerNorm + ReLU ----------------------
__global__ void resid_ln_relu(const float* __restrict__ gat, const float* __restrict__ cb,
                              const float* __restrict__ lin, const float* __restrict__ g,
                              const float* __restrict__ b, float* __restrict__ out) {
    int row = blockIdx.x;
    int t = threadIdx.x;                     // 256 threads, 2 elems each
    size_t base = (size_t)row * DMID;
    float v0 = gat[base + t]       + cb[t]       + lin[base + t];
    float v1 = gat[base + 256 + t] + cb[256 + t] + lin[base + 256 + t];
    float s = v0 + v1;
    float ss = v0 * v0 + v1 * v1;
    #pragma unroll
    for (int o = 16; o > 0; o >>= 1) {
        s  += __shfl_down_sync(0xffffffffu, s, o);
        ss += __shfl_down_sync(0xffffffffu, ss, o);
    }
    __shared__ float shs[8], shss[8];
    __shared__ float mu_sh, inv_sh;
    int w = t >> 5, lane = t & 31;
    if (lane == 0) { shs[w] = s; shss[w] = ss; }
    __syncthreads();
    if (t == 0) {
        float S = 0.f, SS = 0.f;
        #pragma unroll
        for (int i = 0; i < 8; i++) { S += shs[i]; SS += shss[i]; }
        float mu = S * (1.f / DMID);
        float var = SS * (1.f / DMID) - mu * mu;
        mu_sh = mu;
        inv_sh = rsqrtf(var + 1e-5f);
    }
    __syncthreads();
    float mu = mu_sh, inv = inv_sh;
    out[base + t]       = fmaxf((v0 - mu) * inv * g[t]       + b[t],       0.f);
    out[base + 256 + t] = fmaxf((v1 - mu) * inv * g[256 + t] + b[256 + t], 0.f);
}

// ---------------- residual (+bias), no norm --------------------------------
__global__ void resid_add(const float* __restrict__ gat, const float* __restrict__ cb,
                          const float* __restrict__ lin, float* __restrict__ out, int n) {
    int i = blockIdx.x * blockDim.x + threadIdx.x;
    int stride = gridDim.x * blockDim.x;
    for (; i < n; i += stride)
        out[i] = gat[i] + cb[i & (DMID - 1)] + lin[i];
}

// ---------------- host ------------------------------------------------------
static void gemm(const float* A, int lda, const float* B, int ldb,
                 float* C, int ldc, const float* bias,
                 int M, int N, int K, int relu) {
    static const int smem_bytes = SMEM_FLOATS * 4;
    cudaFuncSetAttribute(tf32_gemm_kernel,
                         cudaFuncAttributeMaxDynamicSharedMemorySize, smem_bytes);
    dim3 grid((N + TBN - 1) / TBN, (M + TBM - 1) / TBM);
    tf32_gemm_kernel<<<grid, 256, smem_bytes>>>(A, lda, B, ldb, C, ldc, bias, M, N, K, relu);
}

extern "C" void kernel_launch(void* const* d_in, const int* in_sizes, int n_in,
                              void* d_out, int out_size) {
    const float* x      = (const float*)d_in[0];
    const void*  ei     = d_in[1];
    const float* W_rna  = (const float*)d_in[2];
    const float* b_rna  = (const float*)d_in[3];
    const float* W_prot = (const float*)d_in[4];
    const float* b_prot = (const float*)d_in[5];
    const float* c1_Ws  = (const float*)d_in[6];
    const float* c1_Wd  = (const float*)d_in[7];
    const float* c1_as  = (const float*)d_in[8];
    const float* c1_ad  = (const float*)d_in[9];
    const float* c1_b   = (const float*)d_in[10];
    const float* l1_W   = (const float*)d_in[11];
    const float* l1_b   = (const float*)d_in[12];
    const float* ln_g   = (const float*)d_in[13];
    const float* ln_b   = (const float*)d_in[14];
    const float* c2_Ws  = (const float*)d_in[15];
    const float* c2_Wd  = (const float*)d_in[16];
    const float* c2_as  = (const float*)d_in[17];
    const float* c2_ad  = (const float*)d_in[18];
    const float* c2_b   = (const float*)d_in[19];
    const float* l2_W   = (const float*)d_in[20];
    const float* l2_b   = (const float*)d_in[21];
    const float* agg_W  = (const float*)d_in[22];
    const float* agg_b  = (const float*)d_in[23];
    const float* dr_W   = (const float*)d_in[24];
    const float* dr_b   = (const float*)d_in[25];
    const float* dp_W   = (const float*)d_in[26];
    const float* dp_b   = (const float*)d_in[27];
    const float* rr_W   = (const float*)d_in[28];
    const float* rr_b   = (const float*)d_in[29];
    const float* rp_W   = (const float*)d_in[30];
    const float* rp_b   = (const float*)d_in[31];

    float* out = (float*)d_out;
    float* out_rna  = out;                                  // [NN, 2000]
    float* out_prot = out + (size_t)NN * RNAD;              // [NN, 100]
    float* out_emb  = out + (size_t)NN * (RNAD + PROTD);    // [NN, 128]

    float *xin, *xs, *xd, *lin, *gat, *h, *as_, *ad_, *den, *alpha, *t;
    unsigned* menc;
    int *srcI, *dstI;
    cudaGetSymbolAddress((void**)&xin,  g_xin);
    cudaGetSymbolAddress((void**)&xs,   g_xs);
    cudaGetSymbolAddress((void**)&xd,   g_xd);
    cudaGetSymbolAddress((void**)&lin,  g_lin);
    cudaGetSymbolAddress((void**)&gat,  g_gat);
    cudaGetSymbolAddress((void**)&h,    g_h);
    cudaGetSymbolAddress((void**)&as_,  g_as);
    cudaGetSymbolAddress((void**)&ad_,  g_ad);
    cudaGetSymbolAddress((void**)&menc, g_menc);
    cudaGetSymbolAddress((void**)&den,  g_den);
    cudaGetSymbolAddress((void**)&alpha,g_alpha);
    cudaGetSymbolAddress((void**)&t,    g_t);
    cudaGetSymbolAddress((void**)&srcI, g_src);
    cudaGetSymbolAddress((void**)&dstI, g_dst);

    const int EB = 256;
    const int nEH = EE * NH;
    const int nScatter = EE * 128;

    // ---- decode edge indices (int32/int64 agnostic, clamped) --------------
    detect_fmt<<<1, 32>>>((const unsigned*)ei);
    decode_idx<<<(2 * EE + EB - 1) / EB, EB>>>(ei, srcI, dstI);

    // ---- input embeddings: xin = [x@W_rna+b | x@W_prot+b] -----------------
    gemm(x,          RNAD + PROTD, W_rna,  EMBD, xin,        DIN, b_rna,  NN, EMBD, RNAD,  0);
    gemm(x + RNAD,   RNAD + PROTD, W_prot, EMBD, xin + EMBD, DIN, b_prot, NN, EMBD, PROTD, 0);

    // ================= Block 1 =============================================
    gemm(xin, DIN, c1_Ws, DMID, xs,  DMID, nullptr, NN, DMID, DIN, 0);
    gemm(xin, DIN, c1_Wd, DMID, xd,  DMID, nullptr, NN, DMID, DIN, 0);
    gemm(xin, DIN, l1_W,  DMID, lin, DMID, l1_b,    NN, DMID, DIN, 0);

    att_scores<<<NN, 128>>>(xs, xd, c1_as, c1_ad, as_, ad_);
    zero_u32<<<512, 256>>>((unsigned*)gat, NN * DMID);
    zero_u32<<<64, 256>>>((unsigned*)den, NN * NH);
    zero_u32<<<64, 256>>>(menc, NN * NH);

    edge_alpha_max<<<(nEH + EB - 1) / EB, EB>>>(srcI, dstI, as_, ad_, alpha, menc);
    edge_exp_sum  <<<(nEH + EB - 1) / EB, EB>>>(dstI, alpha, menc, den);
    edge_norm     <<<(nEH + EB - 1) / EB, EB>>>(dstI, alpha, den);
    edge_scatter  <<<(nScatter + EB - 1) / EB, EB>>>(srcI, dstI, alpha, xs, gat);

    resid_ln_relu<<<NN, 256>>>(gat, c1_b, lin, ln_g, ln_b, h);

    // ================= Block 2 =============================================
    gemm(h, DMID, c2_Ws, DMID, xs,  DMID, nullptr, NN, DMID, DMID, 0);
    gemm(h, DMID, c2_Wd, DMID, xd,  DMID, nullptr, NN, DMID, DMID, 0);
    gemm(h, DMID, l2_W,  DMID, lin, DMID, l2_b,    NN, DMID, DMID, 0);

    att_scores<<<NN, 128>>>(xs, xd, c2_as, c2_ad, as_, ad_);
    zero_u32<<<512, 256>>>((unsigned*)gat, NN * DMID);
    zero_u32<<<64, 256>>>((unsigned*)den, NN * NH);
    zero_u32<<<64, 256>>>(menc, NN * NH);

    edge_alpha_max<<<(nEH + EB - 1) / EB, EB>>>(srcI, dstI, as_, ad_, alpha, menc);
    edge_exp_sum  <<<(nEH + EB - 1) / EB, EB>>>(dstI, alpha, menc, den);
    edge_norm     <<<(nEH + EB - 1) / EB, EB>>>(dstI, alpha, den);
    edge_scatter  <<<(nScatter + EB - 1) / EB, EB>>>(srcI, dstI, alpha, xs, gat);

    resid_add<<<512, 256>>>(gat, c2_b, lin, h, NN * DMID);

    // ================= Heads ===============================================
    gemm(h, DMID, agg_W, EMBD, out_emb, EMBD, agg_b, NN, EMBD, DMID, 1);   // emb (relu)

    gemm(out_emb, EMBD, dr_W, EMBD, t, EMBD, dr_b, NN, EMBD, EMBD, 0);     // t1
    gemm(t, EMBD, rr_W, RNAD, out_rna, RNAD, rr_b, NN, RNAD, EMBD, 0);     // rna_recon

    gemm(out_emb, EMBD, dp_W, EMBD, t, EMBD, dp_b, NN, EMBD, EMBD, 0);     // t2
    gemm(t, EMBD, rp_W, PROTD, out_prot, PROTD, rp_b, NN, PROTD, EMBD, 0); // prot_recon
}